// round 14
// baseline (speedup 1.0000x reference)
#include <cuda_runtime.h>
#include <cuda_fp16.h>
#include <cstdint>

#define MM     41
#define SPAD   448           // padded F-type u slots
#define UPAD   512           // total u slots; per-GEMM K = 2*UPAD = 1024
#define NCHUNK 16            // chunks of 32 u
#define RSTR   136           // stage row stride in halfs (128 data + 8 pad)
#define BUFH   (32 * RSTR)

// g_Bfrag[((sd*5 + nt)*32 + ktp)*32 + lane], ktp = pair of k-tiles (32 k)
__device__ uint4  g_Bfrag[2 * 5 * 32 * 32];
__device__ float4 g_meta[SPAD];            // (Cx/2, Cy/2, pk_bits, 0)

__device__ __forceinline__ uint32_t pack_h2(float lo, float hi) {
    uint32_t r;
    asm("cvt.rn.f16x2.f32 %0, %1, %2;" : "=r"(r) : "f"(hi), "f"(lo));
    return r;
}
__device__ __forceinline__ void mma16816(float* d, const uint32_t* a, uint32_t b0, uint32_t b1) {
    asm volatile(
        "mma.sync.aligned.m16n8k16.row.col.f32.f16.f16.f32 "
        "{%0,%1,%2,%3}, {%4,%5,%6,%7}, {%8,%9}, {%0,%1,%2,%3};"
        : "+f"(d[0]), "+f"(d[1]), "+f"(d[2]), "+f"(d[3])
        : "r"(a[0]), "r"(a[1]), "r"(a[2]), "r"(a[3]), "r"(b0), "r"(b1));
}
__device__ __forceinline__ void ldsm4(uint32_t* r, uint32_t saddr) {
    asm volatile("ldmatrix.sync.aligned.m8n8.x4.shared.b16 {%0,%1,%2,%3}, [%4];"
                 : "=r"(r[0]), "=r"(r[1]), "=r"(r[2]), "=r"(r[3]) : "r"(saddr));
}

// B value for GEMM sd (0=S,1=D) at (k, col): k in [0,1024), col in [0,40).
// k = 2u+e, e: 0->Fx, 1->Fy. col = 4j+c: c0=Xout(W1), c1=Yout(W1), c2=Xout(W2), c3=Yout(W2).
__device__ float bwval(int sd, int k, int col, int S,
                       const float2* __restrict__ W1, const float2* __restrict__ W2) {
    int u = k >> 1, e = k & 1;
    int j = col >> 2, c = col & 3;
    float2 w0, w1;
    if (c < 2) {
        if (u >= S) return 0.f;
        w0 = W1[(j * 2 + 0) * S + u];
        w1 = W1[(j * 2 + 1) * S + u];
    } else {
        int m = u - SPAD;
        if (m < 0 || m >= MM) return 0.f;
        w0 = W2[(j * 2 + 0) * MM + m];
        w1 = W2[(j * 2 + 1) * MM + m];
    }
    float wx = 0.5f * (sd == 0 ? (w0.x + w1.x) : (w0.x - w1.x));
    float wy = 0.5f * (sd == 0 ? (w0.y + w1.y) : (w0.y - w1.y));
    if ((c & 1) == 0) return e == 0 ? wx : -wy;    // X output
    return                 e == 0 ? wy :  wx;     // Y output
}

__global__ void repack(const float2* __restrict__ W1, const float2* __restrict__ W2,
                       const float2* __restrict__ C,
                       const int* __restrict__ m_idx, const int* __restrict__ n_idx, int S) {
    int t = blockIdx.x * blockDim.x + threadIdx.x;
    if (t < SPAD) {
        if (t < S) {
            float2 cc = C[t];
            int m = m_idx[t], n = n_idx[t];
            int pk = (20 + m) | ((20 + m + n) << 8) | ((20 + n) << 16);
            g_meta[t] = make_float4(0.5f * cc.x, 0.5f * cc.y, __int_as_float(pk), 0.f);
        } else {
            g_meta[t] = make_float4(0.f, 0.f, __int_as_float(0), 0.f);
        }
    }
    if (t >= 2 * 5 * 32 * 32) return;
    int lane = t & 31, ktp = (t >> 5) & 31, nt = (t >> 10) & 7, sd = t >> 13;
    if (nt >= 5) return;
    int col = nt * 8 + (lane >> 2);
    int kr = (lane & 3) * 2;
    uint32_t r[4];
#pragma unroll
    for (int tt = 0; tt < 2; tt++) {
        int k0 = (2 * ktp + tt) * 16 + kr;
        r[2 * tt + 0] = pack_h2(bwval(sd, k0,     col, S, W1, W2),
                                bwval(sd, k0 + 1, col, S, W1, W2));
        r[2 * tt + 1] = pack_h2(bwval(sd, k0 + 8, col, S, W1, W2),
                                bwval(sd, k0 + 9, col, S, W1, W2));
    }
    g_Bfrag[((sd * 5 + nt) * 32 + ktp) * 32 + lane] = make_uint4(r[0], r[1], r[2], r[3]);
}

// Block = 32 batches (lane=batch), 4 warps = (m-tile x {S,D}); double-buffered chunks.
__global__ __launch_bounds__(128, 4)
void eq_main(const float4* __restrict__ x, const float* __restrict__ task,
             const float2* __restrict__ b1, const float2* __restrict__ b2,
             float4* __restrict__ out, int S) {
    __shared__ __align__(16) float4 E_sh[32 * 41];        // 21 KB; overlaid by Dout later
    __shared__ __align__(16) __half stage[2 * BUFH];      // 17.4 KB
    __shared__ float4 meta_sh[SPAD];                      // 7 KB
    __shared__ float4 pbcbuf[4][32];

    float* Dout = (float*)E_sh;                           // [32][88] after overlay

    const int lane = threadIdx.x & 31;
    const int warp = threadIdx.x >> 5;
    const int tid = threadIdx.x;
    const int b0 = blockIdx.x * 32;

    for (int i = tid; i < 32 * MM; i += 128) {
        int bl = i / MM, k = i - bl * MM;
        E_sh[bl * 41 + k] = x[(size_t)(b0 + bl) * MM + k];
    }
    for (int i = tid; i < SPAD; i += 128) meta_sh[i] = g_meta[i];
    __syncthreads();

    const float4* Eb = &E_sh[lane * 41];
    const uint32_t stage_u = (uint32_t)__cvta_generic_to_shared(stage);

    float PSx = 0.f, PSy = 0.f, PDx = 0.f, PDy = 0.f;
    float d[5][4];
#pragma unroll
    for (int n = 0; n < 5; n++)
#pragma unroll
        for (int q = 0; q < 4; q++) d[n][q] = 0.f;

    const int mt = warp & 1, sd = warp >> 1;
    const uint32_t lroff =
        (uint32_t)((mt * 16 + (lane & 15)) * RSTR + ((lane >> 4) << 3) + sd * 64) * 2u;
    const uint4* bfr = &g_Bfrag[(size_t)sd * 5 * 32 * 32];

    // features for one chunk (8 u per warp) into buffer `buf`:
    // S pair at half-offset 2*ul, D pair at 64 + 2*ul  (ul = u in chunk, 0..31)
    auto features = [&](int ch, int buf) {
        int ul0 = warp * 8;
        int ubase = ch * 32 + ul0;
        __half* bp = stage + buf * BUFH + lane * RSTR;
#pragma unroll
        for (int i = 0; i < 8; i++) {
            int u = ubase + i;
            uint32_t h0 = 0, h1 = 0;
            if (u < SPAD) {
                float4 mtv = meta_sh[u];
                int pk = __float_as_int(mtv.z);
                float4 Em  = Eb[pk & 255];
                float4 Emn = Eb[(pk >> 8) & 255];
                float4 En  = Eb[(pk >> 16) & 255];
                float Asx = Em.x * Emn.x + Em.y * Emn.y + Em.z * Emn.z + Em.w * Emn.w;
                float Asy = Em.y * Emn.x - Em.x * Emn.y + Em.w * Emn.z - Em.z * Emn.w;
                float Ensx = En.x + En.z, Ensy = En.y + En.w;
                float Endx = En.x - En.z, Endy = En.y - En.w;
                float Fsx = Asx * Ensx - Asy * Ensy, Fsy = Asx * Ensy + Asy * Ensx;
                float Fdx = Asx * Endx - Asy * Endy, Fdy = Asx * Endy + Asy * Endx;
                PSx += mtv.x * Fsx - mtv.y * Fsy;  PSy += mtv.x * Fsy + mtv.y * Fsx;
                PDx += mtv.x * Fdx - mtv.y * Fdy;  PDy += mtv.x * Fdy + mtv.y * Fdx;
                h0 = pack_h2(Fsx, Fsy);
                h1 = pack_h2(Fdx, Fdy);
            } else if (u - SPAD < MM) {
                float4 Ek = Eb[u - SPAD];
                h0 = pack_h2(Ek.x + Ek.z, Ek.y + Ek.w);
                h1 = pack_h2(Ek.x - Ek.z, Ek.y - Ek.w);
            }
            int ul = ul0 + i;
            *(uint32_t*)(bp + 2 * ul)      = h0;   // S half
            *(uint32_t*)(bp + 64 + 2 * ul) = h1;   // D half
        }
    };

    features(0, 0);
    __syncthreads();

    int cur = 0;
    for (int ch = 0; ch < NCHUNK; ch++) {
        const int ktbase = ch * 2;         // global ktp (0..31), 2 per chunk
        uint4 bb[5];
#pragma unroll
        for (int n = 0; n < 5; n++)
            bb[n] = bfr[((size_t)n * 32 + ktbase) * 32 + lane];

        if (ch + 1 < NCHUNK) features(ch + 1, cur ^ 1);

        const uint32_t lbase = stage_u + (uint32_t)(cur * BUFH) * 2u + lroff;
#pragma unroll
        for (int ktp = 0; ktp < 2; ktp++) {
            uint4 bbn[5];
            if (ktp == 0) {
#pragma unroll
                for (int n = 0; n < 5; n++)
                    bbn[n] = bfr[((size_t)n * 32 + ktbase + 1) * 32 + lane];
            }
            uint32_t a0[4], a1[4];
            uint32_t ad = lbase + (uint32_t)(ktp * 32) * 2u;
            ldsm4(a0, ad);
            ldsm4(a1, ad + 32);
#pragma unroll
            for (int n = 0; n < 5; n++) {
                mma16816(d[n], a0, bb[n].x, bb[n].y);
                mma16816(d[n], a1, bb[n].z, bb[n].w);
            }
            if (ktp == 0) {
#pragma unroll
                for (int n = 0; n < 5; n++) bb[n] = bbn[n];
            }
        }
        __syncthreads();
        cur ^= 1;
    }

    // ---- epilogue ----
    float4 Ec;
    if (warp == 0) Ec = Eb[20];
    pbcbuf[warp][lane] = make_float4(PSx, PSy, PDx, PDy);
    __syncthreads();

    // Dout [32][88]: cols 0..39 = S outputs (4j + {ASx,ASy,BSx,BSy}), 40..79 = D outputs
#pragma unroll
    for (int n = 0; n < 5; n++) {
        int colg = sd * 40 + n * 8 + (lane & 3) * 2;
        int r0 = mt * 16 + (lane >> 2);
        *(float2*)(Dout + r0 * 88 + colg)       = make_float2(d[n][0], d[n][1]);
        *(float2*)(Dout + (r0 + 8) * 88 + colg) = make_float2(d[n][2], d[n][3]);
    }
    __syncthreads();

    if (warp == 0) {
        float4 s0 = pbcbuf[0][lane], s1 = pbcbuf[1][lane];
        float4 s2 = pbcbuf[2][lane], s3 = pbcbuf[3][lane];
        float PSxT = s0.x + s1.x + s2.x + s3.x, PSyT = s0.y + s1.y + s2.y + s3.y;
        float PDxT = s0.z + s1.z + s2.z + s3.z, PDyT = s0.w + s1.w + s2.w + s3.w;
        float P0x = PSxT + PDxT, P0y = PSyT + PDyT;
        float P1x = PSxT - PDxT, P1y = PSyT - PDyT;

        float p = exp10f(task[(size_t)(b0 + lane) * 4] * 0.1f) * 0.5f;
        float o0x = Ec.x + p * P0x, o0y = Ec.y + p * P0y;
        float o1x = Ec.z + p * P1x, o1y = Ec.w + p * P1y;

        const float* row = Dout + lane * 88;
        float t0x = 0.f, t0y = 0.f, t1x = 0.f, t1y = 0.f;
#pragma unroll
        for (int j = 0; j < 10; j++) {
            float4 Sv = *(const float4*)(row + 4 * j);        // ASx,ASy,BSx,BSy
            float4 Dv = *(const float4*)(row + 40 + 4 * j);   // ADx,ADy,BDx,BDy
            float2 c1 = b1[j], c2 = b2[j];
            float a0x = Sv.x + Dv.x + c1.x, a0y = Sv.y + Dv.y + c1.y;
            float a1x = Sv.x - Dv.x + c1.x, a1y = Sv.y - Dv.y + c1.y;
            float bx0 = Sv.z + Dv.z + c2.x, by0 = Sv.w + Dv.w + c2.y;
            float bx1 = Sv.z - Dv.z + c2.x, by1 = Sv.w - Dv.w + c2.y;
            float n0 = bx0 * bx0 + by0 * by0;
            float sx0 = bx0 * bx0 - by0 * by0, sy0 = 2.f * bx0 * by0;
            t0x += a0x * n0 + a0x * sx0 + a0y * sy0;
            t0y += a0y * n0 + a0x * sy0 - a0y * sx0;
            float n1 = bx1 * bx1 + by1 * by1;
            float sx1 = bx1 * bx1 - by1 * by1, sy1 = 2.f * bx1 * by1;
            t1x += a1x * n1 + a1x * sx1 + a1y * sy1;
            t1y += a1y * n1 + a1x * sy1 - a1y * sx1;
        }
        float sc = 3.1622776601683794e-5f * p * p;
        out[b0 + lane] = make_float4(o0x + sc * t0x, o0y + sc * t0y,
                                     o1x + sc * t1x, o1y + sc * t1y);
    }
}

extern "C" void kernel_launch(void* const* d_in, const int* in_sizes, int n_in,
                              void* d_out, int out_size) {
    const float4* x    = (const float4*)d_in[0];
    const float*  task = (const float*)d_in[1];
    const float2* C    = (const float2*)d_in[2];
    const float2* W1   = (const float2*)d_in[3];
    const float2* b1   = (const float2*)d_in[4];
    const float2* W2   = (const float2*)d_in[5];
    const float2* b2   = (const float2*)d_in[6];
    const int* m_idx   = (const int*)d_in[7];
    const int* n_idx   = (const int*)d_in[8];

    int S = in_sizes[8];
    int B = in_sizes[1] / 4;

    repack<<<(2 * 8 * 32 * 32 + 127) / 128, 128>>>(W1, W2, C, m_idx, n_idx, S);
    eq_main<<<B / 32, 128>>>(x, task, b1, b2, (float4*)d_out, S);
}

// round 15
// speedup vs baseline: 1.0008x; 1.0008x over previous
#include <cuda_runtime.h>
#include <cuda_fp16.h>
#include <cstdint>

#define MM     41
#define SPAD   448           // padded F-type u slots
#define UPAD   512           // total u slots; per-GEMM K = 2*UPAD = 1024
#define NCHUNK 16            // chunks of 32 u
#define RSTR   136           // stage row stride in halfs (128 data + 8 pad)
#define BUFH   (32 * RSTR)

// g_Bfrag[((sd*5 + nt)*32 + ktp)*32 + lane], ktp = pair of k-tiles (32 k)
__device__ uint4  g_Bfrag[2 * 5 * 32 * 32];
__device__ float4 g_meta[SPAD];            // (Cx/2, Cy/2, pk_bits, 0)

__device__ __forceinline__ uint32_t pack_h2(float lo, float hi) {
    uint32_t r;
    asm("cvt.rn.f16x2.f32 %0, %1, %2;" : "=r"(r) : "f"(hi), "f"(lo));
    return r;
}
__device__ __forceinline__ void mma16816(float* d, const uint32_t* a, uint32_t b0, uint32_t b1) {
    asm volatile(
        "mma.sync.aligned.m16n8k16.row.col.f32.f16.f16.f32 "
        "{%0,%1,%2,%3}, {%4,%5,%6,%7}, {%8,%9}, {%0,%1,%2,%3};"
        : "+f"(d[0]), "+f"(d[1]), "+f"(d[2]), "+f"(d[3])
        : "r"(a[0]), "r"(a[1]), "r"(a[2]), "r"(a[3]), "r"(b0), "r"(b1));
}
__device__ __forceinline__ void ldsm4(uint32_t* r, uint32_t saddr) {
    asm volatile("ldmatrix.sync.aligned.m8n8.x4.shared.b16 {%0,%1,%2,%3}, [%4];"
                 : "=r"(r[0]), "=r"(r[1]), "=r"(r[2]), "=r"(r[3]) : "r"(saddr));
}

// B value for GEMM sd (0=S,1=D) at (k, col): k in [0,1024), col in [0,40).
// k = 2u+e, e: 0->Fx, 1->Fy. col = 4j+c: c0=Xout(W1), c1=Yout(W1), c2=Xout(W2), c3=Yout(W2).
__device__ float bwval(int sd, int k, int col, int S,
                       const float2* __restrict__ W1, const float2* __restrict__ W2) {
    int u = k >> 1, e = k & 1;
    int j = col >> 2, c = col & 3;
    float2 w0, w1;
    if (c < 2) {
        if (u >= S) return 0.f;
        w0 = W1[(j * 2 + 0) * S + u];
        w1 = W1[(j * 2 + 1) * S + u];
    } else {
        int m = u - SPAD;
        if (m < 0 || m >= MM) return 0.f;
        w0 = W2[(j * 2 + 0) * MM + m];
        w1 = W2[(j * 2 + 1) * MM + m];
    }
    float wx = 0.5f * (sd == 0 ? (w0.x + w1.x) : (w0.x - w1.x));
    float wy = 0.5f * (sd == 0 ? (w0.y + w1.y) : (w0.y - w1.y));
    if ((c & 1) == 0) return e == 0 ? wx : -wy;    // X output
    return                 e == 0 ? wy :  wx;     // Y output
}

__global__ void repack(const float2* __restrict__ W1, const float2* __restrict__ W2,
                       const float2* __restrict__ C,
                       const int* __restrict__ m_idx, const int* __restrict__ n_idx, int S) {
    int t = blockIdx.x * blockDim.x + threadIdx.x;
    if (t < SPAD) {
        if (t < S) {
            float2 cc = C[t];
            int m = m_idx[t], n = n_idx[t];
            int pk = (20 + m) | ((20 + m + n) << 8) | ((20 + n) << 16);
            g_meta[t] = make_float4(0.5f * cc.x, 0.5f * cc.y, __int_as_float(pk), 0.f);
        } else {
            g_meta[t] = make_float4(0.f, 0.f, __int_as_float(0), 0.f);
        }
    }
    if (t >= 2 * 5 * 32 * 32) return;
    int lane = t & 31, ktp = (t >> 5) & 31, nt = (t >> 10) & 7, sd = t >> 13;
    if (nt >= 5) return;
    int col = nt * 8 + (lane >> 2);
    int kr = (lane & 3) * 2;
    uint32_t r[4];
#pragma unroll
    for (int tt = 0; tt < 2; tt++) {
        int k0 = (2 * ktp + tt) * 16 + kr;
        r[2 * tt + 0] = pack_h2(bwval(sd, k0,     col, S, W1, W2),
                                bwval(sd, k0 + 1, col, S, W1, W2));
        r[2 * tt + 1] = pack_h2(bwval(sd, k0 + 8, col, S, W1, W2),
                                bwval(sd, k0 + 9, col, S, W1, W2));
    }
    g_Bfrag[((sd * 5 + nt) * 32 + ktp) * 32 + lane] = make_uint4(r[0], r[1], r[2], r[3]);
}

// Block = 32 batches (lane=batch), 4 warps = (m-tile x {S,D}); double-buffered chunks.
__global__ __launch_bounds__(128, 4)
void eq_main(const float4* __restrict__ x, const float* __restrict__ task,
             const float2* __restrict__ b1, const float2* __restrict__ b2,
             float4* __restrict__ out, int S) {
    __shared__ __align__(16) float4 E_sh[32 * 41];        // 21 KB; overlaid by Dout later
    __shared__ __align__(16) __half stage[2 * BUFH];      // 17.4 KB
    __shared__ float4 meta_sh[SPAD];                      // 7 KB
    __shared__ float4 pbcbuf[4][32];

    float* Dout = (float*)E_sh;                           // [32][88] after overlay

    const int lane = threadIdx.x & 31;
    const int warp = threadIdx.x >> 5;
    const int tid = threadIdx.x;
    const int b0 = blockIdx.x * 32;

    for (int i = tid; i < 32 * MM; i += 128) {
        int bl = i / MM, k = i - bl * MM;
        E_sh[bl * 41 + k] = x[(size_t)(b0 + bl) * MM + k];
    }
    for (int i = tid; i < SPAD; i += 128) meta_sh[i] = g_meta[i];
    __syncthreads();

    const float4* Eb = &E_sh[lane * 41];
    const uint32_t stage_u = (uint32_t)__cvta_generic_to_shared(stage);

    float PSx = 0.f, PSy = 0.f, PDx = 0.f, PDy = 0.f;
    float d[5][4];
#pragma unroll
    for (int n = 0; n < 5; n++)
#pragma unroll
        for (int q = 0; q < 4; q++) d[n][q] = 0.f;

    const int mt = warp & 1, sd = warp >> 1;
    const uint32_t lroff =
        (uint32_t)((mt * 16 + (lane & 15)) * RSTR + ((lane >> 4) << 3) + sd * 64) * 2u;
    const uint4* bfr = &g_Bfrag[(size_t)sd * 5 * 32 * 32];

    // features for one chunk (8 u per warp) into buffer `buf`:
    // S pair at half-offset 2*ul, D pair at 64 + 2*ul  (ul = u in chunk, 0..31)
    auto features = [&](int ch, int buf) {
        int ul0 = warp * 8;
        int ubase = ch * 32 + ul0;
        __half* bp = stage + buf * BUFH + lane * RSTR;
#pragma unroll
        for (int i = 0; i < 8; i++) {
            int u = ubase + i;
            uint32_t h0 = 0, h1 = 0;
            if (u < SPAD) {
                float4 mtv = meta_sh[u];
                int pk = __float_as_int(mtv.z);
                float4 Em  = Eb[pk & 255];
                float4 Emn = Eb[(pk >> 8) & 255];
                float4 En  = Eb[(pk >> 16) & 255];
                float Asx = Em.x * Emn.x + Em.y * Emn.y + Em.z * Emn.z + Em.w * Emn.w;
                float Asy = Em.y * Emn.x - Em.x * Emn.y + Em.w * Emn.z - Em.z * Emn.w;
                float Ensx = En.x + En.z, Ensy = En.y + En.w;
                float Endx = En.x - En.z, Endy = En.y - En.w;
                float Fsx = Asx * Ensx - Asy * Ensy, Fsy = Asx * Ensy + Asy * Ensx;
                float Fdx = Asx * Endx - Asy * Endy, Fdy = Asx * Endy + Asy * Endx;
                PSx += mtv.x * Fsx - mtv.y * Fsy;  PSy += mtv.x * Fsy + mtv.y * Fsx;
                PDx += mtv.x * Fdx - mtv.y * Fdy;  PDy += mtv.x * Fdy + mtv.y * Fdx;
                h0 = pack_h2(Fsx, Fsy);
                h1 = pack_h2(Fdx, Fdy);
            } else if (u - SPAD < MM) {
                float4 Ek = Eb[u - SPAD];
                h0 = pack_h2(Ek.x + Ek.z, Ek.y + Ek.w);
                h1 = pack_h2(Ek.x - Ek.z, Ek.y - Ek.w);
            }
            int ul = ul0 + i;
            *(uint32_t*)(bp + 2 * ul)      = h0;   // S half
            *(uint32_t*)(bp + 64 + 2 * ul) = h1;   // D half
        }
    };

    features(0, 0);
    __syncthreads();

    int cur = 0;
    for (int ch = 0; ch < NCHUNK; ch++) {
        const int ktbase = ch * 2;         // global ktp (0..31), 2 per chunk
        uint4 bb[5];
#pragma unroll
        for (int n = 0; n < 5; n++)
            bb[n] = bfr[((size_t)n * 32 + ktbase) * 32 + lane];

        if (ch + 1 < NCHUNK) features(ch + 1, cur ^ 1);

        const uint32_t lbase = stage_u + (uint32_t)(cur * BUFH) * 2u + lroff;
#pragma unroll
        for (int ktp = 0; ktp < 2; ktp++) {
            uint4 bbn[5];
            if (ktp == 0) {
#pragma unroll
                for (int n = 0; n < 5; n++)
                    bbn[n] = bfr[((size_t)n * 32 + ktbase + 1) * 32 + lane];
            }
            uint32_t a0[4], a1[4];
            uint32_t ad = lbase + (uint32_t)(ktp * 32) * 2u;
            ldsm4(a0, ad);
            ldsm4(a1, ad + 32);
#pragma unroll
            for (int n = 0; n < 5; n++) {
                mma16816(d[n], a0, bb[n].x, bb[n].y);
                mma16816(d[n], a1, bb[n].z, bb[n].w);
            }
            if (ktp == 0) {
#pragma unroll
                for (int n = 0; n < 5; n++) bb[n] = bbn[n];
            }
        }
        __syncthreads();
        cur ^= 1;
    }

    // ---- epilogue ----
    float4 Ec;
    if (warp == 0) Ec = Eb[20];
    pbcbuf[warp][lane] = make_float4(PSx, PSy, PDx, PDy);
    __syncthreads();

    // Dout [32][88]: cols 0..39 = S outputs (4j + {ASx,ASy,BSx,BSy}), 40..79 = D outputs
#pragma unroll
    for (int n = 0; n < 5; n++) {
        int colg = sd * 40 + n * 8 + (lane & 3) * 2;
        int r0 = mt * 16 + (lane >> 2);
        *(float2*)(Dout + r0 * 88 + colg)       = make_float2(d[n][0], d[n][1]);
        *(float2*)(Dout + (r0 + 8) * 88 + colg) = make_float2(d[n][2], d[n][3]);
    }
    __syncthreads();

    if (warp == 0) {
        float4 s0 = pbcbuf[0][lane], s1 = pbcbuf[1][lane];
        float4 s2 = pbcbuf[2][lane], s3 = pbcbuf[3][lane];
        float PSxT = s0.x + s1.x + s2.x + s3.x, PSyT = s0.y + s1.y + s2.y + s3.y;
        float PDxT = s0.z + s1.z + s2.z + s3.z, PDyT = s0.w + s1.w + s2.w + s3.w;
        float P0x = PSxT + PDxT, P0y = PSyT + PDyT;
        float P1x = PSxT - PDxT, P1y = PSyT - PDyT;

        float p = exp10f(task[(size_t)(b0 + lane) * 4] * 0.1f) * 0.5f;
        float o0x = Ec.x + p * P0x, o0y = Ec.y + p * P0y;
        float o1x = Ec.z + p * P1x, o1y = Ec.w + p * P1y;

        const float* row = Dout + lane * 88;
        float t0x = 0.f, t0y = 0.f, t1x = 0.f, t1y = 0.f;
#pragma unroll
        for (int j = 0; j < 10; j++) {
            float4 Sv = *(const float4*)(row + 4 * j);        // ASx,ASy,BSx,BSy
            float4 Dv = *(const float4*)(row + 40 + 4 * j);   // ADx,ADy,BDx,BDy
            float2 c1 = b1[j], c2 = b2[j];
            float a0x = Sv.x + Dv.x + c1.x, a0y = Sv.y + Dv.y + c1.y;
            float a1x = Sv.x - Dv.x + c1.x, a1y = Sv.y - Dv.y + c1.y;
            float bx0 = Sv.z + Dv.z + c2.x, by0 = Sv.w + Dv.w + c2.y;
            float bx1 = Sv.z - Dv.z + c2.x, by1 = Sv.w - Dv.w + c2.y;
            float n0 = bx0 * bx0 + by0 * by0;
            float sx0 = bx0 * bx0 - by0 * by0, sy0 = 2.f * bx0 * by0;
            t0x += a0x * n0 + a0x * sx0 + a0y * sy0;
            t0y += a0y * n0 + a0x * sy0 - a0y * sx0;
            float n1 = bx1 * bx1 + by1 * by1;
            float sx1 = bx1 * bx1 - by1 * by1, sy1 = 2.f * bx1 * by1;
            t1x += a1x * n1 + a1x * sx1 + a1y * sy1;
            t1y += a1y * n1 + a1x * sy1 - a1y * sx1;
        }
        float sc = 3.1622776601683794e-5f * p * p;
        out[b0 + lane] = make_float4(o0x + sc * t0x, o0y + sc * t0y,
                                     o1x + sc * t1x, o1y + sc * t1y);
    }
}

extern "C" void kernel_launch(void* const* d_in, const int* in_sizes, int n_in,
                              void* d_out, int out_size) {
    const float4* x    = (const float4*)d_in[0];
    const float*  task = (const float*)d_in[1];
    const float2* C    = (const float2*)d_in[2];
    const float2* W1   = (const float2*)d_in[3];
    const float2* b1   = (const float2*)d_in[4];
    const float2* W2   = (const float2*)d_in[5];
    const float2* b2   = (const float2*)d_in[6];
    const int* m_idx   = (const int*)d_in[7];
    const int* n_idx   = (const int*)d_in[8];

    int S = in_sizes[8];
    int B = in_sizes[1] / 4;

    repack<<<(2 * 8 * 32 * 32 + 127) / 128, 128>>>(W1, W2, C, m_idx, n_idx, S);
    eq_main<<<B / 32, 128>>>(x, task, b1, b2, (float4*)d_out, S);
}